// round 5
// baseline (speedup 1.0000x reference)
#include <cuda_runtime.h>

#define NNODE 21
#define NPAD 24
#define HIDD 128
#define HSTR 132            // padded row stride (floats) -> bank-conflict-free row broadcasts
#define TSTEPS 500
#define NEDGE 210

typedef unsigned long long u64;

// ---------------- packed f32x2 helpers ----------------
__device__ __forceinline__ u64 pk2(float lo, float hi) {
    u64 r; asm("mov.b64 %0,{%1,%2};" : "=l"(r) : "f"(lo), "f"(hi)); return r;
}
__device__ __forceinline__ u64 bc2(float v) {
    u64 r; asm("mov.b64 %0,{%1,%1};" : "=l"(r) : "f"(v)); return r;
}
__device__ __forceinline__ u64 fma2(u64 a, u64 b, u64 c) {
    u64 d; asm("fma.rn.f32x2 %0,%1,%2,%3;" : "=l"(d) : "l"(a), "l"(b), "l"(c)); return d;
}
__device__ __forceinline__ void up2(u64 v, float& lo, float& hi) {
    asm("mov.b64 {%0,%1},%2;" : "=f"(lo), "=f"(hi) : "l"(v));
}
__device__ __forceinline__ float sigm(float v) {
    return __fdividef(1.0f, 1.0f + __expf(-v));
}
__device__ __forceinline__ float tanh_(float v) {
    return 1.0f - __fdividef(2.0f, __expf(2.0f * v) + 1.0f);
}

// ---------------- device-global precomputed state ----------------
__device__ float g_A[NNODE * NNODE];
__device__ float g_fold1[6 * HIDD];
__device__ float g_c2[3 * HIDD];
__device__ __align__(16) float g_W2L[3 * HIDD * HIDD];

// ---------------- single fused setup kernel (2 launches total per call) ----------------
__global__ void setup_all(
    const int* __restrict__ ei, const float* __restrict__ ew,
    const float* Wz1, const float* bz1, const float* lzw1, const float* lzb1,
    const float* Wr1, const float* br1, const float* lrw1, const float* lrb1,
    const float* Wh1, const float* bh1, const float* lhw1, const float* lhb1,
    const float* Wz2, const float* bz2, const float* lzw2, const float* lzb2,
    const float* Wr2, const float* br2, const float* lrw2, const float* lrb2,
    const float* Wh2, const float* bh2, const float* lhw2, const float* lhb2) {
    int tid = threadIdx.x;
    if (blockIdx.x == 0) {
        // ---- graph norm ----
        __shared__ float dinv[NNODE];
        if (tid < NNODE) {
            float d = 1.0f;
            for (int e = 0; e < NEDGE; e++)
                if (ei[NEDGE + e] == tid) d += ew[e];
            dinv[tid] = (d > 0.f) ? (1.0f / sqrtf(d)) : 0.0f;
        }
        __syncthreads();
        if (tid < NNODE * NNODE) {
            int i = tid / NNODE, j = tid % NNODE;
            float a = (i == j) ? dinv[i] * dinv[i] : 0.0f;
            for (int e = 0; e < NEDGE; e++)
                if (ei[e] == j && ei[NEDGE + e] == i)
                    a += dinv[j] * ew[e] * dinv[i];
            g_A[tid] = a;
        }
        // ---- layer-1 folds + layer-2 folded biases ----
        if (tid < HIDD) {
            const float* Ws[3] = {Wz1, Wr1, Wh1};
            const float* bs[3] = {bz1, br1, bh1};
            const float* ls[3] = {lzw1, lrw1, lhw1};
            const float* lb[3] = {lzb1, lrb1, lhb1};
            for (int g = 0; g < 3; g++) {
                float v = 0.f, c = 0.f;
                for (int q = 0; q < HIDD; q++) {
                    float l = ls[g][q * HIDD + tid];
                    v += Ws[g][q] * l;
                    c += bs[g][q] * l;
                }
                g_fold1[g * HIDD + tid] = v;
                g_fold1[(3 + g) * HIDD + tid] = c + lb[g][tid];
            }
            const float* b2[3] = {bz2, br2, bh2};
            const float* l2[3] = {lzw2, lrw2, lhw2};
            const float* p2[3] = {lzb2, lrb2, lhb2};
            for (int g = 0; g < 3; g++) {
                float c = 0.f;
                for (int q = 0; q < HIDD; q++) c += b2[g][q] * l2[g][q * HIDD + tid];
                g_c2[g * HIDD + tid] = c + p2[g][tid];
            }
        }
    } else {
        // ---- W2L = W{g}_2 @ l{g}w_2[:128,:]  (384 blocks: g = id>>7, k = id&127) ----
        __shared__ float wrow[HIDD];
        int id = blockIdx.x - 1;
        int g = id >> 7, k = id & 127;
        const float* W = (g == 0) ? Wz2 : ((g == 1) ? Wr2 : Wh2);
        const float* L = (g == 0) ? lzw2 : ((g == 1) ? lrw2 : lhw2);
        if (tid < HIDD) wrow[tid] = W[k * HIDD + tid];
        __syncthreads();
        if (tid < HIDD) {
            float a = 0.f;
            for (int q = 0; q < HIDD; q++) a += wrow[q] * L[q * HIDD + tid];
            g_W2L[g * HIDD * HIDD + k * HIDD + tid] = a;
        }
    }
}

// ---------------- matmul micro-kernel: NM matrices, 3 rows x 4 cols per lane ----------------
// Warp w owns cols [16w,16w+16); lane: fg=lane&3 (4 cols), rg=lane>>2 (3 rows).
// Weights (global, row-major, stride 128): per warp per k only 4 distinct 16B -> 1 wavefront.
template <int NM>
__device__ __forceinline__ void mmN(const float* __restrict__ S,
                                    const float* __restrict__ U0,
                                    const float* __restrict__ U1,
                                    const float* __restrict__ U2,
                                    int i0, int ui, u64 (&A)[NM][3][2]) {
    const ulonglong2* Ua = reinterpret_cast<const ulonglong2*>(U0);
    const ulonglong2* Ub = reinterpret_cast<const ulonglong2*>(U1);
    const ulonglong2* Uc = reinterpret_cast<const ulonglong2*>(U2);
#pragma unroll 2
    for (int k4 = 0; k4 < HIDD / 4; k4++) {
        float sa[3][4];
#pragma unroll
        for (int r = 0; r < 3; r++) {
            float4 q = *reinterpret_cast<const float4*>(S + (i0 + r) * HSTR + k4 * 4);
            sa[r][0] = q.x; sa[r][1] = q.y; sa[r][2] = q.z; sa[r][3] = q.w;
        }
#pragma unroll
        for (int kk = 0; kk < 4; kk++) {
            int k = k4 * 4 + kk;
            ulonglong2 ua = Ua[k * 32 + ui];
            ulonglong2 ub, uc;
            if (NM > 1) ub = Ub[k * 32 + ui];
            if (NM > 2) uc = Uc[k * 32 + ui];
#pragma unroll
            for (int r = 0; r < 3; r++) {
                u64 s = bc2(sa[r][kk]);
                A[0][r][0] = fma2(s, ua.x, A[0][r][0]);
                A[0][r][1] = fma2(s, ua.y, A[0][r][1]);
                if (NM > 1) {
                    A[1][r][0] = fma2(s, ub.x, A[1][r][0]);
                    A[1][r][1] = fma2(s, ub.y, A[1][r][1]);
                }
                if (NM > 2) {
                    A[2][r][0] = fma2(s, uc.x, A[2][r][0]);
                    A[2][r][1] = fma2(s, uc.y, A[2][r][1]);
                }
            }
        }
    }
}

// A-mix: acc += A[i,:21] @ M (M in smem, stride HSTR)
template <int NM>
__device__ __forceinline__ void amixN(const float* __restrict__ sA,
                                      const float* __restrict__ M0,
                                      const float* __restrict__ M1,
                                      int i0, int ui, u64 (&A)[NM][3][2]) {
    const ulonglong2* Ma = reinterpret_cast<const ulonglong2*>(M0);
    const ulonglong2* Mb = reinterpret_cast<const ulonglong2*>(M1);
#pragma unroll
    for (int j = 0; j < NNODE; j++) {
        ulonglong2 ma = Ma[j * (HSTR / 4) + ui];
        ulonglong2 mb;
        if (NM > 1) mb = Mb[j * (HSTR / 4) + ui];
#pragma unroll
        for (int r = 0; r < 3; r++) {
            u64 a = bc2(sA[(i0 + r) * NNODE + j]);
            A[0][r][0] = fma2(a, ma.x, A[0][r][0]);
            A[0][r][1] = fma2(a, ma.y, A[0][r][1]);
            if (NM > 1) {
                A[1][r][0] = fma2(a, mb.x, A[1][r][0]);
                A[1][r][1] = fma2(a, mb.y, A[1][r][1]);
            }
        }
    }
}

// ---------------- main persistent kernel: one CTA per batch element ----------------
#define BIG (NPAD * HSTR)                                   // 3168 floats per state array
#define SMEM_FLOATS (7 * BIG + 504 + 32 + 9 * HIDD)         // 23864 floats = 95456 B

__global__ void __launch_bounds__(256, 1) tgcn_main(
    const float* __restrict__ x,
    const float* __restrict__ Uz1, const float* __restrict__ Ur1, const float* __restrict__ Uh1,
    const float* __restrict__ Uz2, const float* __restrict__ Ur2, const float* __restrict__ Uh2,
    const float* __restrict__ clsw, const float* __restrict__ clsb,
    float* __restrict__ out) {
    extern __shared__ float sm[];
    float* sH1 = sm;
    float* sH2 = sH1 + BIG;
    float* sZ  = sH2 + BIG;
    float* sHR = sZ  + BIG;
    float* sMa = sHR + BIG;
    float* sMb = sMa + BIG;
    float* sMc = sMb + BIG;
    float* sA  = sMc + BIG;            // 504 (24x21, pad rows zero)
    float* sy  = sA + 504;             // 32 (24 used, pads zero)
    float* sv  = sy + 32;              // 9 * 128
    float* svz = sv,         *svr = sv + 128, *svh = sv + 256;
    float* scz = sv + 384,   *scr = sv + 512, *sch = sv + 640;
    float* sc2z = sv + 768,  *sc2r = sv + 896, *sc2h = sv + 1024;

    const int tid = threadIdx.x, b = blockIdx.x;
    const int w = tid >> 5, lane = tid & 31;
    const int fg = lane & 3, rg = lane >> 2;
    const int ui = w * 4 + fg;          // 16B unit index into a 128-float row
    const int f0 = ui * 4;              // first of 4 cols this lane owns
    const int i0 = rg * 3;              // first of 3 rows this lane owns

    for (int i = tid; i < BIG; i += 256) { sH1[i] = 0.f; sH2[i] = 0.f; }
    for (int i = tid; i < 504; i += 256) sA[i] = (i < NNODE * NNODE) ? g_A[i] : 0.f;
    if (tid < 32) sy[tid] = 0.f;
    if (tid < HIDD)
        for (int g = 0; g < 9; g++) sv[g * 128 + tid] = (g < 6) ? g_fold1[g * 128 + tid] : g_c2[(g - 6) * 128 + tid];
    __syncthreads();

    float accS[12];
#pragma unroll
    for (int q = 0; q < 12; q++) accS[q] = 0.f;

    const float* xb = x + (size_t)b * TSTEPS * NNODE;
    const float* W2Lz = g_W2L;
    const float* W2Lr = g_W2L + HIDD * HIDD;
    const float* W2Lh = g_W2L + 2 * HIDD * HIDD;

    for (int t = 0; t < TSTEPS; t++) {
        // y = A @ x_t
        if (tid < NNODE) {
            const float* xr = xb + t * NNODE;
            float a = 0.f;
#pragma unroll
            for (int j = 0; j < NNODE; j++) a += sA[tid * NNODE + j] * xr[j];
            sy[tid] = a;
        }
        __syncthreads();

        // ---- L1 pass A: Z1, R1 (dual matmul over H1) ----
        {
            u64 A[2][3][2] = {};
            mmN<2>(sH1, Uz1, Ur1, nullptr, i0, ui, A);
#pragma unroll
            for (int r = 0; r < 3; r++) {
                int i = i0 + r; float yv = sy[i];
                float v[4], q[4];
                up2(A[0][r][0], v[0], v[1]); up2(A[0][r][1], v[2], v[3]);
                up2(A[1][r][0], q[0], q[1]); up2(A[1][r][1], q[2], q[3]);
                float4 h4 = *reinterpret_cast<const float4*>(sH1 + i * HSTR + f0);
                float h[4] = {h4.x, h4.y, h4.z, h4.w};
                float zz[4], rr[4];
#pragma unroll
                for (int c = 0; c < 4; c++) {
                    int f = f0 + c;
                    zz[c] = sigm(fmaf(yv, svz[f], scz[f]) + v[c]);
                    rr[c] = sigm(fmaf(yv, svr[f], scr[f]) + q[c]) * h[c];
                }
                *reinterpret_cast<float4*>(sZ + i * HSTR + f0) = make_float4(zz[0], zz[1], zz[2], zz[3]);
                *reinterpret_cast<float4*>(sHR + i * HSTR + f0) = make_float4(rr[0], rr[1], rr[2], rr[3]);
            }
        }
        __syncthreads();

        // ---- L1 pass B: Ht1 + blend into H1 ----
        {
            u64 A[1][3][2] = {};
            mmN<1>(sHR, Uh1, nullptr, nullptr, i0, ui, A);
#pragma unroll
            for (int r = 0; r < 3; r++) {
                int i = i0 + r; float yv = sy[i];
                float v[4];
                up2(A[0][r][0], v[0], v[1]); up2(A[0][r][1], v[2], v[3]);
                float4 h4 = *reinterpret_cast<const float4*>(sH1 + i * HSTR + f0);
                float4 z4 = *reinterpret_cast<const float4*>(sZ + i * HSTR + f0);
                float h[4] = {h4.x, h4.y, h4.z, h4.w};
                float z[4] = {z4.x, z4.y, z4.z, z4.w};
                float nh[4];
#pragma unroll
                for (int c = 0; c < 4; c++) {
                    int f = f0 + c;
                    float hh = tanh_(fmaf(yv, svh[f], sch[f]) + v[c]);
                    nh[c] = fmaf(z[c], h[c] - hh, hh);
                }
                *reinterpret_cast<float4*>(sH1 + i * HSTR + f0) = make_float4(nh[0], nh[1], nh[2], nh[3]);
            }
        }
        __syncthreads();

        // ---- L2 pass A: Mz, Mr, Mh = H1 @ W2L{z,r,h} (triple) ----
        {
            u64 A[3][3][2] = {};
            mmN<3>(sH1, W2Lz, W2Lr, W2Lh, i0, ui, A);
#pragma unroll
            for (int r = 0; r < 3; r++) {
                int i = i0 + r;
                float a[4], bq[4], c[4];
                up2(A[0][r][0], a[0], a[1]); up2(A[0][r][1], a[2], a[3]);
                up2(A[1][r][0], bq[0], bq[1]); up2(A[1][r][1], bq[2], bq[3]);
                up2(A[2][r][0], c[0], c[1]); up2(A[2][r][1], c[2], c[3]);
                *reinterpret_cast<float4*>(sMa + i * HSTR + f0) = make_float4(a[0], a[1], a[2], a[3]);
                *reinterpret_cast<float4*>(sMb + i * HSTR + f0) = make_float4(bq[0], bq[1], bq[2], bq[3]);
                *reinterpret_cast<float4*>(sMc + i * HSTR + f0) = make_float4(c[0], c[1], c[2], c[3]);
            }
        }
        __syncthreads();

        // ---- L2 pass B: Z2 = sig(c2z + A-mix(Mz) + H2@Uz2); HR2 = sig(r-branch)*H2 ----
        {
            u64 A[2][3][2];
            u64 cz0 = pk2(sc2z[f0], sc2z[f0 + 1]), cz1 = pk2(sc2z[f0 + 2], sc2z[f0 + 3]);
            u64 cr0 = pk2(sc2r[f0], sc2r[f0 + 1]), cr1 = pk2(sc2r[f0 + 2], sc2r[f0 + 3]);
#pragma unroll
            for (int r = 0; r < 3; r++) {
                A[0][r][0] = cz0; A[0][r][1] = cz1;
                A[1][r][0] = cr0; A[1][r][1] = cr1;
            }
            amixN<2>(sA, sMa, sMb, i0, ui, A);
            mmN<2>(sH2, Uz2, Ur2, nullptr, i0, ui, A);
#pragma unroll
            for (int r = 0; r < 3; r++) {
                int i = i0 + r;
                float v[4], q[4];
                up2(A[0][r][0], v[0], v[1]); up2(A[0][r][1], v[2], v[3]);
                up2(A[1][r][0], q[0], q[1]); up2(A[1][r][1], q[2], q[3]);
                float4 h4 = *reinterpret_cast<const float4*>(sH2 + i * HSTR + f0);
                float h[4] = {h4.x, h4.y, h4.z, h4.w};
                float zz[4], rr[4];
#pragma unroll
                for (int c = 0; c < 4; c++) {
                    zz[c] = sigm(v[c]);
                    rr[c] = sigm(q[c]) * h[c];
                }
                *reinterpret_cast<float4*>(sZ + i * HSTR + f0) = make_float4(zz[0], zz[1], zz[2], zz[3]);
                *reinterpret_cast<float4*>(sHR + i * HSTR + f0) = make_float4(rr[0], rr[1], rr[2], rr[3]);
            }
        }
        __syncthreads();

        // ---- L2 pass D: Ht2 + blend into H2 + output accumulation ----
        {
            u64 A[1][3][2];
            u64 ch0 = pk2(sc2h[f0], sc2h[f0 + 1]), ch1 = pk2(sc2h[f0 + 2], sc2h[f0 + 3]);
#pragma unroll
            for (int r = 0; r < 3; r++) { A[0][r][0] = ch0; A[0][r][1] = ch1; }
            amixN<1>(sA, sMc, nullptr, i0, ui, A);
            mmN<1>(sHR, Uh2, nullptr, nullptr, i0, ui, A);
#pragma unroll
            for (int r = 0; r < 3; r++) {
                int i = i0 + r;
                float v[4];
                up2(A[0][r][0], v[0], v[1]); up2(A[0][r][1], v[2], v[3]);
                float4 h4 = *reinterpret_cast<const float4*>(sH2 + i * HSTR + f0);
                float4 z4 = *reinterpret_cast<const float4*>(sZ + i * HSTR + f0);
                float h[4] = {h4.x, h4.y, h4.z, h4.w};
                float z[4] = {z4.x, z4.y, z4.z, z4.w};
                float nh[4];
#pragma unroll
                for (int c = 0; c < 4; c++) {
                    float hh = tanh_(v[c]);
                    nh[c] = fmaf(z[c], h[c] - hh, hh);
                    if (rg < 7) accS[r * 4 + c] += nh[c];   // rows >= 21 are padding (rg==7)
                }
                *reinterpret_cast<float4*>(sH2 + i * HSTR + f0) = make_float4(nh[0], nh[1], nh[2], nh[3]);
            }
        }
        __syncthreads();
    }

    // ---- final: out[b] = (sum over nodes,time / (21*500)) @ cls_w + cls_b ----
    if (rg < 7) {
        float cs[4];
#pragma unroll
        for (int c = 0; c < 4; c++) cs[c] = accS[c] + accS[4 + c] + accS[8 + c];
        *reinterpret_cast<float4*>(sMa + rg * HIDD + f0) = make_float4(cs[0], cs[1], cs[2], cs[3]);
    }
    __syncthreads();
    if (tid < HIDD) {
        float s = 0.f;
#pragma unroll
        for (int r = 0; r < 7; r++) s += sMa[r * HIDD + tid];
        s *= (1.0f / (float)(NNODE * TSTEPS));
        sMb[tid] = s * clsw[tid];
    }
    __syncthreads();
    if (tid == 0) {
        float s = 0.f;
        for (int f = 0; f < HIDD; f++) s += sMb[f];
        out[b] = s + clsb[0];
    }
}

// ---------------- launch ----------------
extern "C" void kernel_launch(void* const* d_in, const int* in_sizes, int n_in,
                              void* d_out, int out_size) {
    const float* x    = (const float*)d_in[0];
    const int*   ei   = (const int*)d_in[1];
    const float* ew   = (const float*)d_in[2];
    const float* Wz1  = (const float*)d_in[3];
    const float* bz1  = (const float*)d_in[4];
    const float* lzw1 = (const float*)d_in[5];
    const float* lzb1 = (const float*)d_in[6];
    const float* Wr1  = (const float*)d_in[7];
    const float* br1  = (const float*)d_in[8];
    const float* lrw1 = (const float*)d_in[9];
    const float* lrb1 = (const float*)d_in[10];
    const float* Wh1  = (const float*)d_in[11];
    const float* bh1  = (const float*)d_in[12];
    const float* lhw1 = (const float*)d_in[13];
    const float* lhb1 = (const float*)d_in[14];
    const float* Wz2  = (const float*)d_in[15];
    const float* bz2  = (const float*)d_in[16];
    const float* lzw2 = (const float*)d_in[17];
    const float* lzb2 = (const float*)d_in[18];
    const float* Wr2  = (const float*)d_in[19];
    const float* br2  = (const float*)d_in[20];
    const float* lrw2 = (const float*)d_in[21];
    const float* lrb2 = (const float*)d_in[22];
    const float* Wh2  = (const float*)d_in[23];
    const float* bh2  = (const float*)d_in[24];
    const float* lhw2 = (const float*)d_in[25];
    const float* lhb2 = (const float*)d_in[26];
    const float* clsw = (const float*)d_in[27];
    const float* clsb = (const float*)d_in[28];
    float* out = (float*)d_out;

    setup_all<<<385, 448>>>(ei, ew,
        Wz1, bz1, lzw1, lzb1, Wr1, br1, lrw1, lrb1, Wh1, bh1, lhw1, lhb1,
        Wz2, bz2, lzw2, lzb2, Wr2, br2, lrw2, lrb2, Wh2, bh2, lhw2, lhb2);

    const int smem_bytes = SMEM_FLOATS * (int)sizeof(float);
    cudaFuncSetAttribute(tgcn_main, cudaFuncAttributeMaxDynamicSharedMemorySize, smem_bytes);
    tgcn_main<<<64, 256, smem_bytes>>>(
        x,
        lzw1 + HIDD * HIDD, lrw1 + HIDD * HIDD, lhw1 + HIDD * HIDD,
        lzw2 + HIDD * HIDD, lrw2 + HIDD * HIDD, lhw2 + HIDD * HIDD,
        clsw, clsb, out);
}

// round 6
// speedup vs baseline: 1.6694x; 1.6694x over previous
#include <cuda_runtime.h>

#define NNODE 21
#define NPAD 24
#define HIDD 128
#define HSTR 132            // padded smem row stride (floats): conflict-free row broadcasts
#define TSTEPS 500
#define NEDGE 210

typedef unsigned long long u64;

// ---------------- packed f32x2 helpers ----------------
__device__ __forceinline__ u64 pk2(float lo, float hi) {
    u64 r; asm("mov.b64 %0,{%1,%2};" : "=l"(r) : "f"(lo), "f"(hi)); return r;
}
__device__ __forceinline__ u64 bc2(float v) {
    u64 r; asm("mov.b64 %0,{%1,%1};" : "=l"(r) : "f"(v)); return r;
}
__device__ __forceinline__ u64 fma2(u64 a, u64 b, u64 c) {
    u64 d; asm("fma.rn.f32x2 %0,%1,%2,%3;" : "=l"(d) : "l"(a), "l"(b), "l"(c)); return d;
}
__device__ __forceinline__ void up2(u64 v, float& lo, float& hi) {
    asm("mov.b64 {%0,%1},%2;" : "=f"(lo), "=f"(hi) : "l"(v));
}
__device__ __forceinline__ float sigm(float v) {
    return __fdividef(1.0f, 1.0f + __expf(-v));
}
__device__ __forceinline__ float tanh_(float v) {
    return 1.0f - __fdividef(2.0f, __expf(2.0f * v) + 1.0f);
}

// ---------------- cp.async helpers ----------------
__device__ __forceinline__ void cpa16(void* dst, const void* src) {
    unsigned d = (unsigned)__cvta_generic_to_shared(dst);
    asm volatile("cp.async.cg.shared.global [%0], [%1], 16;\n" :: "r"(d), "l"(src));
}
__device__ __forceinline__ void cpcommit() { asm volatile("cp.async.commit_group;\n"); }
template <int N> __device__ __forceinline__ void cpwait() {
    asm volatile("cp.async.wait_group %0;\n" :: "n"(N));
}

// ---------------- device-global precomputed state ----------------
__device__ float g_A[NNODE * NNODE];
__device__ float g_fold1[6 * HIDD];
__device__ float g_c2[3 * HIDD];
__device__ __align__(16) float g_W2L[3 * HIDD * HIDD];

// ---------------- fused setup kernel ----------------
__global__ void setup_all(
    const int* __restrict__ ei, const float* __restrict__ ew,
    const float* Wz1, const float* bz1, const float* lzw1, const float* lzb1,
    const float* Wr1, const float* br1, const float* lrw1, const float* lrb1,
    const float* Wh1, const float* bh1, const float* lhw1, const float* lhb1,
    const float* Wz2, const float* bz2, const float* lzw2, const float* lzb2,
    const float* Wr2, const float* br2, const float* lrw2, const float* lrb2,
    const float* Wh2, const float* bh2, const float* lhw2, const float* lhb2) {
    int tid = threadIdx.x;
    if (blockIdx.x == 0) {
        __shared__ float dinv[NNODE];
        if (tid < NNODE) {
            float d = 1.0f;
            for (int e = 0; e < NEDGE; e++)
                if (ei[NEDGE + e] == tid) d += ew[e];
            dinv[tid] = (d > 0.f) ? (1.0f / sqrtf(d)) : 0.0f;
        }
        __syncthreads();
        if (tid < NNODE * NNODE) {
            int i = tid / NNODE, j = tid % NNODE;
            float a = (i == j) ? dinv[i] * dinv[i] : 0.0f;
            for (int e = 0; e < NEDGE; e++)
                if (ei[e] == j && ei[NEDGE + e] == i)
                    a += dinv[j] * ew[e] * dinv[i];
            g_A[tid] = a;
        }
        if (tid < HIDD) {
            const float* Ws[3] = {Wz1, Wr1, Wh1};
            const float* bs[3] = {bz1, br1, bh1};
            const float* ls[3] = {lzw1, lrw1, lhw1};
            const float* lb[3] = {lzb1, lrb1, lhb1};
            for (int g = 0; g < 3; g++) {
                float v = 0.f, c = 0.f;
                for (int q = 0; q < HIDD; q++) {
                    float l = ls[g][q * HIDD + tid];
                    v += Ws[g][q] * l;
                    c += bs[g][q] * l;
                }
                g_fold1[g * HIDD + tid] = v;
                g_fold1[(3 + g) * HIDD + tid] = c + lb[g][tid];
            }
            const float* b2[3] = {bz2, br2, bh2};
            const float* l2[3] = {lzw2, lrw2, lhw2};
            const float* p2[3] = {lzb2, lrb2, lhb2};
            for (int g = 0; g < 3; g++) {
                float c = 0.f;
                for (int q = 0; q < HIDD; q++) c += b2[g][q] * l2[g][q * HIDD + tid];
                g_c2[g * HIDD + tid] = c + p2[g][tid];
            }
        }
    } else {
        __shared__ float wrow[HIDD];
        int id = blockIdx.x - 1;
        int g = id >> 7, k = id & 127;
        const float* W = (g == 0) ? Wz2 : ((g == 1) ? Wr2 : Wh2);
        const float* L = (g == 0) ? lzw2 : ((g == 1) ? lrw2 : lhw2);
        if (tid < HIDD) wrow[tid] = W[k * HIDD + tid];
        __syncthreads();
        if (tid < HIDD) {
            float a = 0.f;
            for (int q = 0; q < HIDD; q++) a += wrow[q] * L[q * HIDD + tid];
            g_W2L[g * HIDD * HIDD + k * HIDD + tid] = a;
        }
    }
}

// ---------------- staged-weight matmul ----------------
// Stage buffer layout: [buf(2)][m(3)][k(32)][col(128)] floats. Chunk = 32 k rows (16KB/matrix).
#define CHUNK_F 4096                  // floats per matrix chunk (32*128)
#define BUFSTRIDE (3 * CHUNK_F)       // floats per buffer (3 matrices)

template <int NM>
__device__ __forceinline__ void stage(float* buf, const float* G0, const float* G1,
                                      const float* G2, int c, int tid) {
    const float* Gs[3] = {G0, G1, G2};
#pragma unroll
    for (int m = 0; m < NM; m++) {
        const float* src = Gs[m] + c * CHUNK_F + tid * 4;
        float* dst = buf + m * CHUNK_F + tid * 4;
#pragma unroll
        for (int q = 0; q < 4; q++) cpa16(dst + q * 1024, src + q * 1024);
    }
}

// Compute 32 k's from staged buffer B. Lane owns 3 rows (i0..i0+2) x 4 cols (unit ui).
template <int NM>
__device__ __forceinline__ void mm32(const float* __restrict__ S, int kbase,
                                     const float* __restrict__ B,
                                     int i0, int ui, u64 (&A)[NM][3][2]) {
#pragma unroll 2
    for (int k4 = 0; k4 < 8; k4++) {
        float sa[3][4];
#pragma unroll
        for (int r = 0; r < 3; r++) {
            float4 q = *reinterpret_cast<const float4*>(S + (i0 + r) * HSTR + kbase + k4 * 4);
            sa[r][0] = q.x; sa[r][1] = q.y; sa[r][2] = q.z; sa[r][3] = q.w;
        }
#pragma unroll
        for (int kk = 0; kk < 4; kk++) {
            int k = k4 * 4 + kk;
            ulonglong2 ua, ub, uc;
            ua = *(reinterpret_cast<const ulonglong2*>(B + k * HIDD) + ui);
            if (NM > 1) ub = *(reinterpret_cast<const ulonglong2*>(B + CHUNK_F + k * HIDD) + ui);
            if (NM > 2) uc = *(reinterpret_cast<const ulonglong2*>(B + 2 * CHUNK_F + k * HIDD) + ui);
#pragma unroll
            for (int r = 0; r < 3; r++) {
                u64 s = bc2(sa[r][kk]);
                A[0][r][0] = fma2(s, ua.x, A[0][r][0]);
                A[0][r][1] = fma2(s, ua.y, A[0][r][1]);
                if (NM > 1) {
                    A[1][r][0] = fma2(s, ub.x, A[1][r][0]);
                    A[1][r][1] = fma2(s, ub.y, A[1][r][1]);
                }
                if (NM > 2) {
                    A[2][r][0] = fma2(s, uc.x, A[2][r][0]);
                    A[2][r][1] = fma2(s, uc.y, A[2][r][1]);
                }
            }
        }
    }
}

// Full pass: double-buffered staging + compute, accumulating into A.
template <int NM>
__device__ __forceinline__ void run_mm(const float* __restrict__ S,
                                       const float* G0, const float* G1, const float* G2,
                                       float* sw, int tid, int i0, int ui,
                                       u64 (&A)[NM][3][2]) {
    stage<NM>(sw, G0, G1, G2, 0, tid); cpcommit();
#pragma unroll 1
    for (int c = 0; c < 4; c++) {
        if (c < 3) { stage<NM>(sw + ((c + 1) & 1) * BUFSTRIDE, G0, G1, G2, c + 1, tid); cpcommit(); cpwait<1>(); }
        else cpwait<0>();
        __syncthreads();
        mm32<NM>(S, c * 32, sw + (c & 1) * BUFSTRIDE, i0, ui, A);
        __syncthreads();
    }
}

// A-mix: acc += A[i,:21] @ M (M in smem, stride HSTR)
template <int NM>
__device__ __forceinline__ void amixN(const float* __restrict__ sA,
                                      const float* __restrict__ M0,
                                      const float* __restrict__ M1,
                                      int i0, int ui, u64 (&A)[NM][3][2]) {
    const ulonglong2* Ma = reinterpret_cast<const ulonglong2*>(M0);
    const ulonglong2* Mb = reinterpret_cast<const ulonglong2*>(M1);
#pragma unroll
    for (int j = 0; j < NNODE; j++) {
        ulonglong2 ma = Ma[j * (HSTR / 4) + ui];
        ulonglong2 mb;
        if (NM > 1) mb = Mb[j * (HSTR / 4) + ui];
#pragma unroll
        for (int r = 0; r < 3; r++) {
            u64 a = bc2(sA[(i0 + r) * NNODE + j]);
            A[0][r][0] = fma2(a, ma.x, A[0][r][0]);
            A[0][r][1] = fma2(a, ma.y, A[0][r][1]);
            if (NM > 1) {
                A[1][r][0] = fma2(a, mb.x, A[1][r][0]);
                A[1][r][1] = fma2(a, mb.y, A[1][r][1]);
            }
        }
    }
}

// ---------------- main persistent kernel: one CTA per batch element ----------------
#define BIG (NPAD * HSTR)                                   // 3168 floats per state array
#define STAGE_F (2 * BUFSTRIDE)                             // 24576 floats
#define SMEM_FLOATS (7 * BIG + 504 + 32 + 9 * HIDD + STAGE_F) // 48488 floats = 193952 B

__global__ void __launch_bounds__(256, 1) tgcn_main(
    const float* __restrict__ x,
    const float* __restrict__ Uz1, const float* __restrict__ Ur1, const float* __restrict__ Uh1,
    const float* __restrict__ Uz2, const float* __restrict__ Ur2, const float* __restrict__ Uh2,
    const float* __restrict__ clsw, const float* __restrict__ clsb,
    float* __restrict__ out) {
    extern __shared__ float sm[];
    float* sH1 = sm;
    float* sH2 = sH1 + BIG;
    float* sZ  = sH2 + BIG;
    float* sHR = sZ  + BIG;
    float* sMa = sHR + BIG;
    float* sMb = sMa + BIG;
    float* sMc = sMb + BIG;
    float* sA  = sMc + BIG;            // 504 (24x21)
    float* sy  = sA + 504;             // 32
    float* sv  = sy + 32;              // 9 * 128
    float* sw  = sv + 9 * HIDD;        // stage buffers (16B-aligned by construction)
    float* svz = sv,         *svr = sv + 128, *svh = sv + 256;
    float* scz = sv + 384,   *scr = sv + 512, *sch = sv + 640;
    float* sc2z = sv + 768,  *sc2r = sv + 896, *sc2h = sv + 1024;

    const int tid = threadIdx.x, b = blockIdx.x;
    const int w = tid >> 5, lane = tid & 31;
    const int fg = lane & 3, rg = lane >> 2;
    const int ui = w * 4 + fg;          // 16B unit (4 cols) this lane owns
    const int f0 = ui * 4;
    const int i0 = rg * 3;              // 3 rows this lane owns (rows 21-23 are padding)

    for (int i = tid; i < BIG; i += 256) { sH1[i] = 0.f; sH2[i] = 0.f; }
    for (int i = tid; i < 504; i += 256) sA[i] = (i < NNODE * NNODE) ? g_A[i] : 0.f;
    if (tid < 32) sy[tid] = 0.f;
    if (tid < HIDD)
        for (int g = 0; g < 9; g++)
            sv[g * 128 + tid] = (g < 6) ? g_fold1[g * 128 + tid] : g_c2[(g - 6) * 128 + tid];
    __syncthreads();

    float accS[12];
#pragma unroll
    for (int q = 0; q < 12; q++) accS[q] = 0.f;

    const float* xb = x + (size_t)b * TSTEPS * NNODE;
    const float* W2Lz = g_W2L;
    const float* W2Lr = g_W2L + HIDD * HIDD;
    const float* W2Lh = g_W2L + 2 * HIDD * HIDD;

    for (int t = 0; t < TSTEPS; t++) {
        // y = A @ x_t (x row usually L1-resident; latency negligible per model)
        if (tid < NNODE) {
            const float* xr = xb + t * NNODE;
            float a = 0.f;
#pragma unroll
            for (int j = 0; j < NNODE; j++) a += sA[tid * NNODE + j] * xr[j];
            sy[tid] = a;
        }
        // (sy visibility is ordered by run_mm's internal barriers before any epilogue read)

        // ---- L1 pass A: Z1, R1 (dual matmul over H1, weights staged) ----
        {
            u64 A[2][3][2] = {};
            run_mm<2>(sH1, Uz1, Ur1, nullptr, sw, tid, i0, ui, A);
#pragma unroll
            for (int r = 0; r < 3; r++) {
                int i = i0 + r; float yv = sy[i];
                float v[4], q[4];
                up2(A[0][r][0], v[0], v[1]); up2(A[0][r][1], v[2], v[3]);
                up2(A[1][r][0], q[0], q[1]); up2(A[1][r][1], q[2], q[3]);
                float4 h4 = *reinterpret_cast<const float4*>(sH1 + i * HSTR + f0);
                float h[4] = {h4.x, h4.y, h4.z, h4.w};
                float zz[4], rr[4];
#pragma unroll
                for (int c = 0; c < 4; c++) {
                    int f = f0 + c;
                    zz[c] = sigm(fmaf(yv, svz[f], scz[f]) + v[c]);
                    rr[c] = sigm(fmaf(yv, svr[f], scr[f]) + q[c]) * h[c];
                }
                *reinterpret_cast<float4*>(sZ + i * HSTR + f0) = make_float4(zz[0], zz[1], zz[2], zz[3]);
                *reinterpret_cast<float4*>(sHR + i * HSTR + f0) = make_float4(rr[0], rr[1], rr[2], rr[3]);
            }
        }

        // ---- L1 pass B: Ht1 + blend into H1 ----
        {
            u64 A[1][3][2] = {};
            run_mm<1>(sHR, Uh1, nullptr, nullptr, sw, tid, i0, ui, A);
#pragma unroll
            for (int r = 0; r < 3; r++) {
                int i = i0 + r; float yv = sy[i];
                float v[4];
                up2(A[0][r][0], v[0], v[1]); up2(A[0][r][1], v[2], v[3]);
                float4 h4 = *reinterpret_cast<const float4*>(sH1 + i * HSTR + f0);
                float4 z4 = *reinterpret_cast<const float4*>(sZ + i * HSTR + f0);
                float h[4] = {h4.x, h4.y, h4.z, h4.w};
                float z[4] = {z4.x, z4.y, z4.z, z4.w};
                float nh[4];
#pragma unroll
                for (int c = 0; c < 4; c++) {
                    int f = f0 + c;
                    float hh = tanh_(fmaf(yv, svh[f], sch[f]) + v[c]);
                    nh[c] = fmaf(z[c], h[c] - hh, hh);
                }
                *reinterpret_cast<float4*>(sH1 + i * HSTR + f0) = make_float4(nh[0], nh[1], nh[2], nh[3]);
            }
        }

        // ---- L2 pass A: Mz, Mr, Mh = H1 @ W2L{z,r,h} (triple, staged) ----
        {
            u64 A[3][3][2] = {};
            run_mm<3>(sH1, W2Lz, W2Lr, W2Lh, sw, tid, i0, ui, A);
#pragma unroll
            for (int r = 0; r < 3; r++) {
                int i = i0 + r;
                float a[4], bq[4], c[4];
                up2(A[0][r][0], a[0], a[1]); up2(A[0][r][1], a[2], a[3]);
                up2(A[1][r][0], bq[0], bq[1]); up2(A[1][r][1], bq[2], bq[3]);
                up2(A[2][r][0], c[0], c[1]); up2(A[2][r][1], c[2], c[3]);
                *reinterpret_cast<float4*>(sMa + i * HSTR + f0) = make_float4(a[0], a[1], a[2], a[3]);
                *reinterpret_cast<float4*>(sMb + i * HSTR + f0) = make_float4(bq[0], bq[1], bq[2], bq[3]);
                *reinterpret_cast<float4*>(sMc + i * HSTR + f0) = make_float4(c[0], c[1], c[2], c[3]);
            }
        }

        // ---- L2 pass B: Z2 / R2 branch (amix + H2 matmul, staged) ----
        {
            u64 A[2][3][2];
            u64 cz0 = pk2(sc2z[f0], sc2z[f0 + 1]), cz1 = pk2(sc2z[f0 + 2], sc2z[f0 + 3]);
            u64 cr0 = pk2(sc2r[f0], sc2r[f0 + 1]), cr1 = pk2(sc2r[f0 + 2], sc2r[f0 + 3]);
#pragma unroll
            for (int r = 0; r < 3; r++) {
                A[0][r][0] = cz0; A[0][r][1] = cz1;
                A[1][r][0] = cr0; A[1][r][1] = cr1;
            }
            amixN<2>(sA, sMa, sMb, i0, ui, A);
            run_mm<2>(sH2, Uz2, Ur2, nullptr, sw, tid, i0, ui, A);
#pragma unroll
            for (int r = 0; r < 3; r++) {
                int i = i0 + r;
                float v[4], q[4];
                up2(A[0][r][0], v[0], v[1]); up2(A[0][r][1], v[2], v[3]);
                up2(A[1][r][0], q[0], q[1]); up2(A[1][r][1], q[2], q[3]);
                float4 h4 = *reinterpret_cast<const float4*>(sH2 + i * HSTR + f0);
                float h[4] = {h4.x, h4.y, h4.z, h4.w};
                float zz[4], rr[4];
#pragma unroll
                for (int c = 0; c < 4; c++) {
                    zz[c] = sigm(v[c]);
                    rr[c] = sigm(q[c]) * h[c];
                }
                *reinterpret_cast<float4*>(sZ + i * HSTR + f0) = make_float4(zz[0], zz[1], zz[2], zz[3]);
                *reinterpret_cast<float4*>(sHR + i * HSTR + f0) = make_float4(rr[0], rr[1], rr[2], rr[3]);
            }
        }

        // ---- L2 pass D: Ht2 + blend into H2 + output accumulation ----
        {
            u64 A[1][3][2];
            u64 ch0 = pk2(sc2h[f0], sc2h[f0 + 1]), ch1 = pk2(sc2h[f0 + 2], sc2h[f0 + 3]);
#pragma unroll
            for (int r = 0; r < 3; r++) { A[0][r][0] = ch0; A[0][r][1] = ch1; }
            amixN<1>(sA, sMc, nullptr, i0, ui, A);
            run_mm<1>(sHR, Uh2, nullptr, nullptr, sw, tid, i0, ui, A);
#pragma unroll
            for (int r = 0; r < 3; r++) {
                int i = i0 + r;
                float v[4];
                up2(A[0][r][0], v[0], v[1]); up2(A[0][r][1], v[2], v[3]);
                float4 h4 = *reinterpret_cast<const float4*>(sH2 + i * HSTR + f0);
                float4 z4 = *reinterpret_cast<const float4*>(sZ + i * HSTR + f0);
                float h[4] = {h4.x, h4.y, h4.z, h4.w};
                float z[4] = {z4.x, z4.y, z4.z, z4.w};
                float nh[4];
#pragma unroll
                for (int c = 0; c < 4; c++) {
                    float hh = tanh_(v[c]);
                    nh[c] = fmaf(z[c], h[c] - hh, hh);
                    if (rg < 7) accS[r * 4 + c] += nh[c];
                }
                *reinterpret_cast<float4*>(sH2 + i * HSTR + f0) = make_float4(nh[0], nh[1], nh[2], nh[3]);
            }
        }
        __syncthreads();   // H2/accS complete before next step's sy write + L1A reads
    }

    // ---- final: out[b] = (sum over nodes,time / (21*500)) @ cls_w + cls_b ----
    if (rg < 7) {
        float cs[4];
#pragma unroll
        for (int c = 0; c < 4; c++) cs[c] = accS[c] + accS[4 + c] + accS[8 + c];
        *reinterpret_cast<float4*>(sMa + rg * HIDD + f0) = make_float4(cs[0], cs[1], cs[2], cs[3]);
    }
    __syncthreads();
    if (tid < HIDD) {
        float s = 0.f;
#pragma unroll
        for (int r = 0; r < 7; r++) s += sMa[r * HIDD + tid];
        s *= (1.0f / (float)(NNODE * TSTEPS));
        sMb[tid] = s * clsw[tid];
    }
    __syncthreads();
    if (tid == 0) {
        float s = 0.f;
        for (int f = 0; f < HIDD; f++) s += sMb[f];
        out[b] = s + clsb[0];
    }
}

// ---------------- launch ----------------
extern "C" void kernel_launch(void* const* d_in, const int* in_sizes, int n_in,
                              void* d_out, int out_size) {
    const float* x    = (const float*)d_in[0];
    const int*   ei   = (const int*)d_in[1];
    const float* ew   = (const float*)d_in[2];
    const float* Wz1  = (const float*)d_in[3];
    const float* bz1  = (const float*)d_in[4];
    const float* lzw1 = (const float*)d_in[5];
    const float* lzb1 = (const float*)d_in[6];
    const float* Wr1  = (const float*)d_in[7];
    const float* br1  = (const float*)d_in[8];
    const float* lrw1 = (const float*)d_in[9];
    const float* lrb1 = (const float*)d_in[10];
    const float* Wh1  = (const float*)d_in[11];
    const float* bh1  = (const float*)d_in[12];
    const float* lhw1 = (const float*)d_in[13];
    const float* lhb1 = (const float*)d_in[14];
    const float* Wz2  = (const float*)d_in[15];
    const float* bz2  = (const float*)d_in[16];
    const float* lzw2 = (const float*)d_in[17];
    const float* lzb2 = (const float*)d_in[18];
    const float* Wr2  = (const float*)d_in[19];
    const float* br2  = (const float*)d_in[20];
    const float* lrw2 = (const float*)d_in[21];
    const float* lrb2 = (const float*)d_in[22];
    const float* Wh2  = (const float*)d_in[23];
    const float* bh2  = (const float*)d_in[24];
    const float* lhw2 = (const float*)d_in[25];
    const float* lhb2 = (const float*)d_in[26];
    const float* clsw = (const float*)d_in[27];
    const float* clsb = (const float*)d_in[28];
    float* out = (float*)d_out;

    setup_all<<<385, 448>>>(ei, ew,
        Wz1, bz1, lzw1, lzb1, Wr1, br1, lrw1, lrb1, Wh1, bh1, lhw1, lhb1,
        Wz2, bz2, lzw2, lzb2, Wr2, br2, lrw2, lrb2, Wh2, bh2, lhw2, lhb2);

    const int smem_bytes = SMEM_FLOATS * (int)sizeof(float);  // 193952
    cudaFuncSetAttribute(tgcn_main, cudaFuncAttributeMaxDynamicSharedMemorySize, smem_bytes);
    tgcn_main<<<64, 256, smem_bytes>>>(
        x,
        lzw1 + HIDD * HIDD, lrw1 + HIDD * HIDD, lhw1 + HIDD * HIDD,
        lzw2 + HIDD * HIDD, lrw2 + HIDD * HIDD, lhw2 + HIDD * HIDD,
        clsw, clsb, out);
}